// round 3
// baseline (speedup 1.0000x reference)
#include <cuda_runtime.h>
#include <math.h>

#define NBLK 296
#define B_ 32
#define NF_ 16
#define N_ 192
#define D_ 256
#define S_ 21
#define BS_ 672
#define BN_ 6144

typedef unsigned long long u64t;

/* ------------------------- scratch globals ------------------------- */
__device__ float g_xln[BN_ * D_];
__device__ float g_k[BN_ * D_];
__device__ float g_v[BN_ * D_];
__device__ float g_slots[BS_ * D_];
__device__ float g_slots_ln[BS_ * D_];
__device__ float g_q[BS_ * D_];
__device__ float g_attn[B_ * S_ * N_];
__device__ float g_upd[BS_ * D_];
__device__ float g_gi[BS_ * 3 * D_];
__device__ float g_gh[BS_ * 3 * D_];
__device__ float g_h[BS_ * D_];
__device__ float g_hln[BS_ * D_];
__device__ float g_hidden[BS_ * D_];

/* ------------------------- grid barrier ---------------------------- */
__device__ unsigned g_bar_count = 0;
__device__ volatile unsigned g_bar_gen = 0;

__device__ __forceinline__ void gsync() {
    __syncthreads();
    if (threadIdx.x == 0) {
        unsigned gen = g_bar_gen;
        __threadfence();
        if (atomicAdd(&g_bar_count, 1u) == NBLK - 1) {
            g_bar_count = 0;
            __threadfence();
            g_bar_gen = gen + 1;
        } else {
            while (g_bar_gen == gen) { __nanosleep(32); }
        }
        __threadfence();
    }
    __syncthreads();
}

/* ------------------------- f32x2 helpers --------------------------- */
__device__ __forceinline__ u64t fma2(u64t a, u64t b, u64t c) {
    u64t d;
    asm("fma.rn.f32x2 %0,%1,%2,%3;" : "=l"(d) : "l"(a), "l"(b), "l"(c));
    return d;
}
__device__ __forceinline__ u64t pk2(float x) {
    u64t r;
    asm("mov.b64 %0,{%1,%1};" : "=l"(r) : "f"(x));
    return r;
}
__device__ __forceinline__ float2 upk2(u64t v) {
    float lo, hi;
    asm("mov.b64 {%0,%1},%2;" : "=f"(lo), "=f"(hi) : "l"(v));
    return make_float2(lo, hi);
}

/* ---------------- warp-level LayerNorm, 8 elems/lane --------------- */
__device__ __forceinline__ void warp_ln8(const float* __restrict__ src,
                                         float* __restrict__ dst,
                                         const float* __restrict__ gamma,
                                         const float* __restrict__ beta,
                                         int lane) {
    float4 x0 = *(const float4*)(src + lane * 8);
    float4 x1 = *(const float4*)(src + lane * 8 + 4);
    float s = x0.x + x0.y + x0.z + x0.w + x1.x + x1.y + x1.z + x1.w;
    float q = x0.x * x0.x + x0.y * x0.y + x0.z * x0.z + x0.w * x0.w
            + x1.x * x1.x + x1.y * x1.y + x1.z * x1.z + x1.w * x1.w;
#pragma unroll
    for (int o = 16; o; o >>= 1) {
        s += __shfl_xor_sync(0xffffffffu, s, o);
        q += __shfl_xor_sync(0xffffffffu, q, o);
    }
    float m = s * (1.f / 256.f);
    float var = q * (1.f / 256.f) - m * m;
    float rstd = rsqrtf(var + 1e-5f);
    float4 g0 = *(const float4*)(gamma + lane * 8);
    float4 g1 = *(const float4*)(gamma + lane * 8 + 4);
    float4 b0 = *(const float4*)(beta + lane * 8);
    float4 b1 = *(const float4*)(beta + lane * 8 + 4);
    float4 o0, o1;
    o0.x = (x0.x - m) * rstd * g0.x + b0.x;
    o0.y = (x0.y - m) * rstd * g0.y + b0.y;
    o0.z = (x0.z - m) * rstd * g0.z + b0.z;
    o0.w = (x0.w - m) * rstd * g0.w + b0.w;
    o1.x = (x1.x - m) * rstd * g1.x + b1.x;
    o1.y = (x1.y - m) * rstd * g1.y + b1.y;
    o1.z = (x1.z - m) * rstd * g1.z + b1.z;
    o1.w = (x1.w - m) * rstd * g1.w + b1.w;
    *(float4*)(dst + lane * 8) = o0;
    *(float4*)(dst + lane * 8 + 4) = o1;
}

/* ------------------------- tiled GEMM phase ------------------------ */
/* C[M,N] = A[M,256] @ W[N,256]^T + bias (+relu/+residual)            */
template <int CASE>
__device__ void gemm_phase(float* sh,
                           const float* __restrict__ W0,
                           const float* __restrict__ W1p,
                           const float* __restrict__ c0,
                           const float* __restrict__ c1) {
    constexpr int M = (CASE == 0) ? BN_ : BS_;
    constexpr int N = (CASE == 2) ? 768 : 256;
    constexpr int TM = (M + 63) / 64;
    constexpr int TN = N / 64;
    constexpr int TZ = (CASE == 0 || CASE == 2) ? 2 : 1;
    constexpr int TT = TM * TN * TZ;
    constexpr int K = 256;

    float* As = sh;
    float* Bs = sh + 16 * 68;

    int tid = threadIdx.x;
    int tx = tid & 15, ty = tid >> 4;
    int lrow = tid >> 2;
    int lcol = (tid & 3) << 2;

    for (int t = blockIdx.x; t < TT; t += NBLK) {
        int z = t / (TM * TN);
        int rem = t - z * (TM * TN);
        int my = rem / TN;
        int nx = rem - my * TN;

        const float* A;
        float* C;
        const float* res = nullptr;
        if (CASE == 0)      { A = g_xln;      C = z ? g_v : g_k; }
        else if (CASE == 1) { A = g_slots_ln; C = g_q; }
        else if (CASE == 2) { A = z ? g_slots : g_upd;
                              C = z ? g_gh    : g_gi; }
        else if (CASE == 3) { A = g_hln;      C = g_hidden; }
        else                { A = g_hidden;   C = g_slots; res = g_h; }
        const float* Bw   = z ? W1p : W0;
        const float* bias = z ? c1  : c0;

        int m0 = my * 64, n0 = nx * 64;
        u64t acc[4][2] = {};

        for (int k0 = 0; k0 < K; k0 += 16) {
            float4 av = make_float4(0.f, 0.f, 0.f, 0.f);
            int gm = m0 + lrow;
            if ((M % 64 == 0) || gm < M)
                av = *(const float4*)(A + (size_t)gm * K + k0 + lcol);
            As[(lcol + 0) * 68 + lrow] = av.x;
            As[(lcol + 1) * 68 + lrow] = av.y;
            As[(lcol + 2) * 68 + lrow] = av.z;
            As[(lcol + 3) * 68 + lrow] = av.w;

            float4 bv = *(const float4*)(Bw + (size_t)(n0 + lrow) * K + k0 + lcol);
            Bs[(lcol + 0) * 68 + lrow] = bv.x;
            Bs[(lcol + 1) * 68 + lrow] = bv.y;
            Bs[(lcol + 2) * 68 + lrow] = bv.z;
            Bs[(lcol + 3) * 68 + lrow] = bv.w;
            __syncthreads();

#pragma unroll
            for (int kk = 0; kk < 16; kk++) {
                float4 a4 = *(const float4*)&As[kk * 68 + (ty << 2)];
                const u64t* bp = (const u64t*)&Bs[kk * 68 + (tx << 2)];
                u64t b0 = bp[0], b1 = bp[1];
                u64t a0 = pk2(a4.x), a1 = pk2(a4.y), a2 = pk2(a4.z), a3 = pk2(a4.w);
                acc[0][0] = fma2(a0, b0, acc[0][0]);
                acc[0][1] = fma2(a0, b1, acc[0][1]);
                acc[1][0] = fma2(a1, b0, acc[1][0]);
                acc[1][1] = fma2(a1, b1, acc[1][1]);
                acc[2][0] = fma2(a2, b0, acc[2][0]);
                acc[2][1] = fma2(a2, b1, acc[2][1]);
                acc[3][0] = fma2(a3, b0, acc[3][0]);
                acc[3][1] = fma2(a3, b1, acc[3][1]);
            }
            __syncthreads();
        }

#pragma unroll
        for (int i = 0; i < 4; i++) {
            int gm = m0 + (ty << 2) + i;
            if ((M % 64 != 0) && gm >= M) continue;
            int gn = n0 + (tx << 2);
            float2 c01 = upk2(acc[i][0]);
            float2 c23 = upk2(acc[i][1]);
            float4 c = make_float4(c01.x, c01.y, c23.x, c23.y);
            c.x += bias[gn + 0];
            c.y += bias[gn + 1];
            c.z += bias[gn + 2];
            c.w += bias[gn + 3];
            if (CASE == 3) {
                c.x = fmaxf(c.x, 0.f); c.y = fmaxf(c.y, 0.f);
                c.z = fmaxf(c.z, 0.f); c.w = fmaxf(c.w, 0.f);
            }
            if (CASE == 4) {
                const float* rp = res + (size_t)gm * N + gn;
                c.x += rp[0]; c.y += rp[1]; c.z += rp[2]; c.w += rp[3];
            }
            *(float4*)(C + (size_t)gm * N + gn) = c;
        }
    }
}

/* ------------------------- other phases ---------------------------- */
__device__ void dots_phase(float* sh, float* __restrict__ aout, int f) {
    int tid = threadIdx.x;
    int wid = tid >> 5, lane = tid & 31;
    for (int task = blockIdx.x; task < B_ * 4; task += NBLK) {
        int b = task >> 2, quarter = task & 3;
        for (int i = tid; i < S_ * D_; i += 256)
            sh[i] = g_q[(size_t)b * S_ * D_ + i];
        __syncthreads();
#pragma unroll 1
        for (int p = 0; p < 6; p++) {
            int n = quarter * 48 + wid * 6 + p;
            const u64t* kr = (const u64t*)(g_k + ((size_t)b * N_ + n) * D_);
            u64t k2[4];
#pragma unroll
            for (int i = 0; i < 4; i++) k2[i] = kr[i * 32 + lane];
            float dv[S_];
#pragma unroll
            for (int s = 0; s < S_; s++) {
                const u64t* qp = (const u64t*)&sh[s * D_];
                u64t p2 = 0;
#pragma unroll
                for (int i = 0; i < 4; i++) p2 = fma2(k2[i], qp[i * 32 + lane], p2);
                float2 pf = upk2(p2);
                float pv = pf.x + pf.y;
#pragma unroll
                for (int o = 16; o; o >>= 1) pv += __shfl_xor_sync(0xffffffffu, pv, o);
                dv[s] = pv * 0.0625f;
            }
            float mx = -1e30f;
#pragma unroll
            for (int s = 0; s < S_; s++) mx = fmaxf(mx, dv[s]);
            float sum = 0.f;
#pragma unroll
            for (int s = 0; s < S_; s++) { dv[s] = expf(dv[s] - mx); sum += dv[s]; }
            float inv = 1.f / sum;
            if (lane == 0) {
#pragma unroll
                for (int s = 0; s < S_; s++) {
                    float a = dv[s] * inv + 1e-8f;
                    g_attn[((size_t)b * S_ + s) * N_ + n] = a;
                    if (aout)
                        aout[(((size_t)b * NF_ + f) * S_ + s) * N_ + n] = a;
                }
            }
        }
        __syncthreads();
    }
}

__device__ void updates_phase(float* sh) {
    int tid = threadIdx.x;
    float* inv = sh + S_ * N_;
    for (int task = blockIdx.x; task < B_ * 4; task += NBLK) {
        int b = task >> 2, dq = task & 3;
        int d = dq * 64 + (tid & 63);
        int ty = tid >> 6;
        for (int i = tid; i < S_ * N_; i += 256)
            sh[i] = g_attn[(size_t)b * S_ * N_ + i];
        __syncthreads();
        if (tid < S_) {
            float s = 0.f;
            for (int j = 0; j < N_; j++) s += sh[tid * N_ + j];
            inv[tid] = 1.f / s;
        }
        __syncthreads();
        float acc[6] = {0.f, 0.f, 0.f, 0.f, 0.f, 0.f};
        const float* vb = g_v + (size_t)b * N_ * D_;
        for (int j = 0; j < N_; j++) {
            float vj = vb[(size_t)j * D_ + d];
#pragma unroll
            for (int u = 0; u < 6; u++) {
                int s = ty + u * 4;
                if (s < S_) acc[u] += sh[s * N_ + j] * vj;
            }
        }
#pragma unroll
        for (int u = 0; u < 6; u++) {
            int s = ty + u * 4;
            if (s < S_)
                g_upd[((size_t)b * S_ + s) * D_ + d] = acc[u] * inv[s];
        }
        __syncthreads();
    }
}

__device__ __forceinline__ float sigm(float x) { return 1.f / (1.f + expf(-x)); }

__device__ void gru_ln_phase(const float* __restrict__ gff,
                             const float* __restrict__ beff) {
    int tid = threadIdx.x;
    int wid = tid >> 5, lane = tid & 31;
    for (int r = blockIdx.x * 8 + wid; r < BS_; r += NBLK * 8) {
        const float* gi = g_gi + (size_t)r * 768;
        const float* gh = g_gh + (size_t)r * 768;
        const float* sl = g_slots + (size_t)r * 256;
        float h[8];
        float s = 0.f, q = 0.f;
#pragma unroll
        for (int c = 0; c < 2; c++) {
            int d = lane * 8 + c * 4;
            float4 ir = *(const float4*)(gi + d);
            float4 iz = *(const float4*)(gi + 256 + d);
            float4 in_ = *(const float4*)(gi + 512 + d);
            float4 hr = *(const float4*)(gh + d);
            float4 hz = *(const float4*)(gh + 256 + d);
            float4 hn = *(const float4*)(gh + 512 + d);
            float4 sv = *(const float4*)(sl + d);
            float rr, zz, nn;
            rr = sigm(ir.x + hr.x); zz = sigm(iz.x + hz.x);
            nn = tanhf(in_.x + rr * hn.x);
            h[c * 4 + 0] = (1.f - zz) * nn + zz * sv.x;
            rr = sigm(ir.y + hr.y); zz = sigm(iz.y + hz.y);
            nn = tanhf(in_.y + rr * hn.y);
            h[c * 4 + 1] = (1.f - zz) * nn + zz * sv.y;
            rr = sigm(ir.z + hr.z); zz = sigm(iz.z + hz.z);
            nn = tanhf(in_.z + rr * hn.z);
            h[c * 4 + 2] = (1.f - zz) * nn + zz * sv.z;
            rr = sigm(ir.w + hr.w); zz = sigm(iz.w + hz.w);
            nn = tanhf(in_.w + rr * hn.w);
            h[c * 4 + 3] = (1.f - zz) * nn + zz * sv.w;
        }
#pragma unroll
        for (int j = 0; j < 8; j++) { s += h[j]; q += h[j] * h[j]; }
#pragma unroll
        for (int o = 16; o; o >>= 1) {
            s += __shfl_xor_sync(0xffffffffu, s, o);
            q += __shfl_xor_sync(0xffffffffu, q, o);
        }
        float m = s * (1.f / 256.f);
        float var = q * (1.f / 256.f) - m * m;
        float rstd = rsqrtf(var + 1e-5f);
        float* hp = g_h + (size_t)r * 256;
        float* lp = g_hln + (size_t)r * 256;
#pragma unroll
        for (int c = 0; c < 2; c++) {
            int d = lane * 8 + c * 4;
            float4 gm4 = *(const float4*)(gff + d);
            float4 bt4 = *(const float4*)(beff + d);
            float4 hv = make_float4(h[c * 4], h[c * 4 + 1], h[c * 4 + 2], h[c * 4 + 3]);
            float4 lo;
            lo.x = (hv.x - m) * rstd * gm4.x + bt4.x;
            lo.y = (hv.y - m) * rstd * gm4.y + bt4.y;
            lo.z = (hv.z - m) * rstd * gm4.z + bt4.z;
            lo.w = (hv.w - m) * rstd * gm4.w + bt4.w;
            *(float4*)(hp + d) = hv;
            *(float4*)(lp + d) = lo;
        }
    }
}

/* ------------------------- mega kernel ----------------------------- */
__global__ __launch_bounds__(256, 2) void mega_kernel(
    const float* __restrict__ inputs, const float* __restrict__ noise,
    const float* __restrict__ mu, const float* __restrict__ sigma,
    const float* __restrict__ Wq, const float* __restrict__ bq,
    const float* __restrict__ Wk, const float* __restrict__ bk,
    const float* __restrict__ Wv, const float* __restrict__ bv,
    const float* __restrict__ W1, const float* __restrict__ b1,
    const float* __restrict__ W2, const float* __restrict__ b2,
    const float* __restrict__ Wih, const float* __restrict__ bih,
    const float* __restrict__ Whh, const float* __restrict__ bhh,
    const float* __restrict__ gin, const float* __restrict__ bein,
    const float* __restrict__ gsl, const float* __restrict__ besl,
    const float* __restrict__ gff, const float* __restrict__ beff,
    float* __restrict__ out_slots, float* __restrict__ out_attn) {

    __shared__ __align__(16) float sh[5408];
    int tid = threadIdx.x;
    int wid = tid >> 5, lane = tid & 31;

    /* init slots */
    for (int r = blockIdx.x; r < BS_; r += NBLK) {
        int i = r * 256 + tid;
        g_slots[i] = mu[tid] + sigma[tid] * noise[i];
    }
    gsync();

    for (int f = 0; f < NF_; f++) {
        /* input LN (gather frame) */
        for (int r = blockIdx.x * 8 + wid; r < BN_; r += NBLK * 8) {
            int b = r / N_, hw = r - b * N_;
            const float* src = inputs + (((size_t)b * NF_ + f) * N_ + hw) * D_;
            warp_ln8(src, g_xln + (size_t)r * D_, gin, bein, lane);
        }
        gsync();
        gemm_phase<0>(sh, Wk, Wv, bk, bv);
        gsync();

        for (int it = 0; it < 3; it++) {
            /* slot LN */
            for (int r = blockIdx.x * 8 + wid; r < BS_; r += NBLK * 8)
                warp_ln8(g_slots + (size_t)r * D_, g_slots_ln + (size_t)r * D_,
                         gsl, besl, lane);
            gsync();
            gemm_phase<1>(sh, Wq, Wq, bq, bq);
            gsync();
            dots_phase(sh, (it == 2) ? out_attn : nullptr, f);
            gsync();
            updates_phase(sh);
            gsync();
            gemm_phase<2>(sh, Wih, Whh, bih, bhh);
            gsync();
            gru_ln_phase(gff, beff);
            gsync();
            gemm_phase<3>(sh, W1, W1, b1, b1);
            gsync();
            gemm_phase<4>(sh, W2, W2, b2, b2);
            gsync();
        }
    }

    /* final copy: first 20 slots per batch */
    for (int idx = blockIdx.x * 256 + tid; idx < B_ * 20 * D_; idx += NBLK * 256) {
        int d = idx & 255;
        int s = (idx >> 8) % 20;
        int b = idx / (20 * 256);
        out_slots[idx] = g_slots[((size_t)(b * S_) + s) * D_ + d];
    }
}

/* ------------------------------------------------------------------ */
extern "C" void kernel_launch(void* const* d_in, const int* in_sizes, int n_in,
                              void* d_out, int out_size) {
    const float* inputs = (const float*)d_in[0];
    const float* noise  = (const float*)d_in[1];
    const float* mu     = (const float*)d_in[2];
    const float* sigma  = (const float*)d_in[3];
    const float* Wq = (const float*)d_in[4];  const float* bq = (const float*)d_in[5];
    const float* Wk = (const float*)d_in[6];  const float* bk = (const float*)d_in[7];
    const float* Wv = (const float*)d_in[8];  const float* bv = (const float*)d_in[9];
    const float* W1 = (const float*)d_in[10]; const float* b1 = (const float*)d_in[11];
    const float* W2 = (const float*)d_in[12]; const float* b2 = (const float*)d_in[13];
    const float* Wih = (const float*)d_in[14]; const float* bih = (const float*)d_in[15];
    const float* Whh = (const float*)d_in[16]; const float* bhh = (const float*)d_in[17];
    const float* gin = (const float*)d_in[18]; const float* bein = (const float*)d_in[19];
    const float* gsl = (const float*)d_in[20]; const float* besl = (const float*)d_in[21];
    const float* gff = (const float*)d_in[22]; const float* beff = (const float*)d_in[23];

    float* out = (float*)d_out;
    float* out_slots = out;
    float* out_attn = out + (size_t)B_ * 20 * D_;

    mega_kernel<<<NBLK, 256>>>(inputs, noise, mu, sigma,
                               Wq, bq, Wk, bk, Wv, bv, W1, b1, W2, b2,
                               Wih, bih, Whh, bhh,
                               gin, bein, gsl, besl, gff, beff,
                               out_slots, out_attn);
}

// round 5
// speedup vs baseline: 1.5040x; 1.5040x over previous
#include <cuda_runtime.h>
#include <math.h>

#define B_ 32
#define NF_ 16
#define N_ 192
#define D_ 256
#define S_ 21
#define NP 11            /* slot row-pairs (ceil(21/2)) */
#define G 8              /* blocks per batch */
#define NBLK 256
#define SMEM_BYTES 84480 /* 21120 floats */

typedef unsigned long long u64;

/* ---------------- transposed weights ------------------------------- */
__device__ float g_wqt[D_ * D_];
__device__ float g_wkt[D_ * D_];
__device__ float g_wvt[D_ * D_];
__device__ float g_w1t[D_ * D_];
__device__ float g_w2t[D_ * D_];
__device__ float g_wiht[D_ * 3 * D_]; /* [k][gcol] */
__device__ float g_whht[D_ * 3 * D_];

/* ---------------- state scratch ------------------------------------ */
__device__ float g_k[B_ * N_ * D_];
__device__ float g_v[B_ * N_ * D_];
__device__ float g_slots[B_ * S_ * D_];
__device__ float g_q[B_ * S_ * D_];
__device__ float g_attn[B_ * S_ * N_];
__device__ float g_upd[B_ * S_ * D_];
__device__ float g_h[B_ * S_ * D_];
__device__ float g_hidden[B_ * S_ * D_];

/* ---------------- barriers ----------------------------------------- */
__device__ unsigned g_gcnt = 0;
__device__ volatile unsigned g_ggen = 0;
__device__ unsigned g_bcnt[B_ * 32];
__device__ volatile unsigned g_bgen[B_ * 32];

__device__ __forceinline__ void gsync_all() {
    __threadfence();
    __syncthreads();
    if (threadIdx.x == 0) {
        unsigned g0 = g_ggen;
        if (atomicAdd(&g_gcnt, 1u) == NBLK - 1) {
            g_gcnt = 0;
            __threadfence();
            g_ggen = g0 + 1;
        } else {
            while (g_ggen == g0) __nanosleep(64);
        }
        __threadfence();
    }
    __syncthreads();
}

__device__ __forceinline__ void bsync(int bb) {
    __threadfence();
    __syncthreads();
    if (threadIdx.x == 0) {
        volatile unsigned* gen = &g_bgen[bb * 32];
        unsigned g0 = *gen;
        if (atomicAdd(&g_bcnt[bb * 32], 1u) == G - 1) {
            g_bcnt[bb * 32] = 0;
            __threadfence();
            *gen = g0 + 1;
        } else {
            while (*gen == g0) __nanosleep(32);
        }
        __threadfence();
    }
    __syncthreads();
}

/* ---------------- f32x2 helpers ------------------------------------ */
__device__ __forceinline__ void fma2p(u64& acc, u64 a, u64 b) {
    asm("fma.rn.f32x2 %0,%1,%2,%3;" : "=l"(acc) : "l"(a), "l"(b), "l"(acc));
}
__device__ __forceinline__ u64 pk2(float x) {
    u64 r;
    asm("mov.b64 %0,{%1,%1};" : "=l"(r) : "f"(x));
    return r;
}
__device__ __forceinline__ float2 upk(u64 v) {
    float2 r;
    asm("mov.b64 {%0,%1},%2;" : "=f"(r.x), "=f"(r.y) : "l"(v));
    return r;
}
__device__ __forceinline__ float sigm(float x) { return 1.f / (1.f + expf(-x)); }

/* ---------------- warp LN: one 256-row -> 8 regs/lane --------------- */
__device__ __forceinline__ void ln_row(const float* __restrict__ src,
                                       const float* __restrict__ gm,
                                       const float* __restrict__ bt,
                                       int lane, float* o) {
    float4 x0 = *(const float4*)(src + lane * 8);
    float4 x1 = *(const float4*)(src + lane * 8 + 4);
    float s = x0.x + x0.y + x0.z + x0.w + x1.x + x1.y + x1.z + x1.w;
    float q = x0.x * x0.x + x0.y * x0.y + x0.z * x0.z + x0.w * x0.w
            + x1.x * x1.x + x1.y * x1.y + x1.z * x1.z + x1.w * x1.w;
#pragma unroll
    for (int off = 16; off; off >>= 1) {
        s += __shfl_xor_sync(0xffffffffu, s, off);
        q += __shfl_xor_sync(0xffffffffu, q, off);
    }
    float m = s * (1.f / 256.f);
    float rstd = rsqrtf(q * (1.f / 256.f) - m * m + 1e-5f);
    float4 g0 = *(const float4*)(gm + lane * 8);
    float4 g1 = *(const float4*)(gm + lane * 8 + 4);
    float4 b0 = *(const float4*)(bt + lane * 8);
    float4 b1 = *(const float4*)(bt + lane * 8 + 4);
    o[0] = (x0.x - m) * rstd * g0.x + b0.x;
    o[1] = (x0.y - m) * rstd * g0.y + b0.y;
    o[2] = (x0.z - m) * rstd * g0.z + b0.z;
    o[3] = (x0.w - m) * rstd * g0.w + b0.w;
    o[4] = (x1.x - m) * rstd * g1.x + b1.x;
    o[5] = (x1.y - m) * rstd * g1.y + b1.y;
    o[6] = (x1.z - m) * rstd * g1.z + b1.z;
    o[7] = (x1.w - m) * rstd * g1.w + b1.w;
}

/* pack 21 raw smem rows (stride 256) -> pair-major u64 a2[11*256] */
__device__ __forceinline__ void pack21(const float* __restrict__ raw,
                                       u64* __restrict__ a2, int tid) {
    for (int idx = tid; idx < NP * 256; idx += 256) {
        int p = idx >> 8, k = idx & 255;
        float lo = raw[(2 * p) * 256 + k];
        float hi = (2 * p + 1 < S_) ? raw[(2 * p + 1) * 256 + k] : 0.f;
        float2 v = make_float2(lo, hi);
        a2[idx] = *(u64*)&v;
    }
}

/* pack 21 global rows -> pair-major u64 a2[11*256] */
__device__ __forceinline__ void pack21g(const float* __restrict__ src,
                                        u64* __restrict__ a2, int tid) {
    for (int idx = tid; idx < NP * 256; idx += 256) {
        int p = idx >> 8, k = idx & 255;
        float lo = src[(2 * p) * 256 + k];
        float hi = (2 * p + 1 < S_) ? src[(2 * p + 1) * 256 + k] : 0.f;
        float2 v = make_float2(lo, hi);
        a2[idx] = *(u64*)&v;
    }
}

/* ------------------------- mega kernel ----------------------------- */
__global__ __launch_bounds__(256, 2) void mega_kernel(
    const float* __restrict__ inputs, const float* __restrict__ noise,
    const float* __restrict__ mu, const float* __restrict__ sigma,
    const float* __restrict__ Wq, const float* __restrict__ bq,
    const float* __restrict__ Wk, const float* __restrict__ bk,
    const float* __restrict__ Wv, const float* __restrict__ bv,
    const float* __restrict__ W1, const float* __restrict__ b1,
    const float* __restrict__ W2, const float* __restrict__ b2,
    const float* __restrict__ Wih, const float* __restrict__ bih,
    const float* __restrict__ Whh, const float* __restrict__ bhh,
    const float* __restrict__ gin, const float* __restrict__ bein,
    const float* __restrict__ gsl, const float* __restrict__ besl,
    const float* __restrict__ gff, const float* __restrict__ beff,
    float* __restrict__ out_slots, float* __restrict__ out_attn) {

    extern __shared__ __align__(16) float sh[];
    int tid = threadIdx.x;
    int wid = tid >> 5, lane = tid & 31;
    int bb = blockIdx.x >> 3;
    int j = blockIdx.x & 7;
    int d0 = j * 32;

    /* ---- transpose weights + init slots (grid-wide, once) ---- */
    {
        int gt = blockIdx.x * 256 + tid; /* 0..65535 */
        int k = gt >> 8, c = gt & 255;
        g_wqt[k * 256 + c] = Wq[c * 256 + k];
        g_wkt[k * 256 + c] = Wk[c * 256 + k];
        g_wvt[k * 256 + c] = Wv[c * 256 + k];
        g_w1t[k * 256 + c] = W1[c * 256 + k];
        g_w2t[k * 256 + c] = W2[c * 256 + k];
        for (int idx = gt; idx < 768 * 256; idx += NBLK * 256) {
            int kk = idx / 768, cc = idx - kk * 768;
            g_wiht[idx] = Wih[cc * 256 + kk];
            g_whht[idx] = Whh[cc * 256 + kk];
        }
        for (int idx = gt; idx < B_ * S_ * 256; idx += NBLK * 256) {
            int d = idx & 255;
            g_slots[idx] = mu[d] + sigma[d] * noise[idx];
        }
    }
    gsync_all();

    const size_t so = (size_t)bb * S_ * D_;   /* slot-block offset */
    const size_t ko = (size_t)bb * N_ * D_;   /* kv offset */

    for (int f = 0; f < NF_; f++) {
        /* =============== KV: block j owns rows [24j,24j+24) ========= */
        {
            float* raw = sh;                 /* 24*256 */
            u64* a2 = (u64*)(sh + 6144);     /* 12*256 */
            int r0 = j * 24;
#pragma unroll 1
            for (int i = 0; i < 3; i++) {
                int lr = wid * 3 + i;
                const float* src = inputs + (((size_t)bb * NF_ + f) * N_ + r0 + lr) * D_;
                float o[8];
                ln_row(src, gin, bein, lane, o);
                *(float4*)(raw + lr * 256 + lane * 8) = make_float4(o[0], o[1], o[2], o[3]);
                *(float4*)(raw + lr * 256 + lane * 8 + 4) = make_float4(o[4], o[5], o[6], o[7]);
            }
            __syncthreads();
            for (int idx = tid; idx < 12 * 256; idx += 256) {
                int p = idx >> 8, k = idx & 255;
                float2 v = make_float2(raw[(2 * p) * 256 + k], raw[(2 * p + 1) * 256 + k]);
                a2[idx] = *(u64*)&v;
            }
            __syncthreads();
#pragma unroll 1
            for (int kv = 0; kv < 2; kv++) {
                const float* wt = kv ? g_wvt : g_wkt;
                float bias = kv ? bv[tid] : bk[tid];
                float* dst = kv ? g_v : g_k;
                u64 acc[12];
#pragma unroll
                for (int p = 0; p < 12; p++) acc[p] = 0;
#pragma unroll 4
                for (int k = 0; k < 256; k++) {
                    u64 bw = pk2(wt[k * 256 + tid]);
#pragma unroll
                    for (int p = 0; p < 12; p++) fma2p(acc[p], a2[p * 256 + k], bw);
                }
#pragma unroll
                for (int p = 0; p < 12; p++) {
                    float2 c = upk(acc[p]);
                    dst[ko + (size_t)(r0 + 2 * p) * D_ + tid] = c.x + bias;
                    dst[ko + (size_t)(r0 + 2 * p + 1) * D_ + tid] = c.y + bias;
                }
            }
        }
        bsync(bb);

        for (int it = 0; it < 3; it++) {
            /* =============== q: LN(slots) @ WqT, cols [d0,d0+32) ===== */
            {
                float* raw = sh;                    /* 21*256 */
                u64* a2q = (u64*)(sh + 5376);       /* 11*256 */
                u64* part = (u64*)(sh + 11008);     /* 8*11*32 */
#pragma unroll 1
                for (int r = wid; r < S_; r += 8) {
                    float o[8];
                    ln_row(g_slots + so + (size_t)r * D_, gsl, besl, lane, o);
                    *(float4*)(raw + r * 256 + lane * 8) = make_float4(o[0], o[1], o[2], o[3]);
                    *(float4*)(raw + r * 256 + lane * 8 + 4) = make_float4(o[4], o[5], o[6], o[7]);
                }
                __syncthreads();
                pack21(raw, a2q, tid);
                __syncthreads();
                int c = tid & 31, w = tid >> 5, col = d0 + c;
                u64 acc[NP];
#pragma unroll
                for (int p = 0; p < NP; p++) acc[p] = 0;
#pragma unroll 4
                for (int kk = 0; kk < 32; kk++) {
                    int k = w * 32 + kk;
                    u64 bw = pk2(g_wqt[k * 256 + col]);
#pragma unroll
                    for (int p = 0; p < NP; p++) fma2p(acc[p], a2q[p * 256 + k], bw);
                }
#pragma unroll
                for (int p = 0; p < NP; p++) part[(w * NP + p) * 32 + c] = acc[p];
                __syncthreads();
                for (int o = tid; o < NP * 32; o += 256) {
                    int p = o >> 5, cc = o & 31;
                    float2 s = make_float2(0.f, 0.f);
#pragma unroll
                    for (int w2 = 0; w2 < 8; w2++) {
                        float2 v = upk(part[(w2 * NP + p) * 32 + cc]);
                        s.x += v.x; s.y += v.y;
                    }
                    float bias = bq[d0 + cc];
                    g_q[so + (size_t)(2 * p) * D_ + d0 + cc] = s.x + bias;
                    if (2 * p + 1 < S_)
                        g_q[so + (size_t)(2 * p + 1) * D_ + d0 + cc] = s.y + bias;
                }
            }
            bsync(bb);

            /* =============== dots+softmax: pixels [24j,24j+24) ======= */
            {
                float* qs = sh; /* 21*256 */
                for (int i = tid; i < S_ * 256; i += 256) qs[i] = g_q[so + i];
                __syncthreads();
                float* aout = (it == 2) ? out_attn : nullptr;
#pragma unroll 1
                for (int pi = 0; pi < 3; pi++) {
                    int n = j * 24 + wid * 3 + pi;
                    const u64* kr = (const u64*)(g_k + ko + (size_t)n * D_);
                    u64 k2[4];
#pragma unroll
                    for (int i = 0; i < 4; i++) k2[i] = kr[i * 32 + lane];
                    float dv[S_];
#pragma unroll
                    for (int s = 0; s < S_; s++) {
                        const u64* qp = (const u64*)&qs[s * 256];
                        u64 p2 = 0;
#pragma unroll
                        for (int i = 0; i < 4; i++) fma2p(p2, k2[i], qp[i * 32 + lane]);
                        float2 pf = upk(p2);
                        float pv = pf.x + pf.y;
#pragma unroll
                        for (int off = 16; off; off >>= 1)
                            pv += __shfl_xor_sync(0xffffffffu, pv, off);
                        dv[s] = pv * 0.0625f;
                    }
                    float mx = -1e30f;
#pragma unroll
                    for (int s = 0; s < S_; s++) mx = fmaxf(mx, dv[s]);
                    float sum = 0.f;
#pragma unroll
                    for (int s = 0; s < S_; s++) { dv[s] = expf(dv[s] - mx); sum += dv[s]; }
                    float inv = 1.f / sum;
                    if (lane == 0) {
#pragma unroll
                        for (int s = 0; s < S_; s++) {
                            float a = dv[s] * inv + 1e-8f;
                            g_attn[((size_t)bb * S_ + s) * N_ + n] = a;
                            if (aout)
                                aout[(((size_t)bb * NF_ + f) * S_ + s) * N_ + n] = a;
                        }
                    }
                }
            }
            bsync(bb);

            /* =============== updates: cols [d0,d0+32), n-split ======= */
            {
                u64* at2 = (u64*)sh;               /* 11*192 */
                float* rinv = sh + 4224;           /* 21 */
                u64* part = (u64*)(sh + 4248);     /* 8*11*32 */
                for (int idx = tid; idx < NP * N_; idx += 256) {
                    int p = idx / N_, nn = idx - p * N_;
                    float lo = g_attn[((size_t)bb * S_ + 2 * p) * N_ + nn];
                    float hi = (2 * p + 1 < S_)
                             ? g_attn[((size_t)bb * S_ + 2 * p + 1) * N_ + nn] : 0.f;
                    float2 v = make_float2(lo, hi);
                    at2[idx] = *(u64*)&v;
                }
                __syncthreads();
                if (tid < S_) {
                    int p = tid >> 1;
                    float s = 0.f;
                    for (int n = 0; n < N_; n++) {
                        float2 v = upk(at2[p * N_ + n]);
                        s += (tid & 1) ? v.y : v.x;
                    }
                    rinv[tid] = 1.f / s;
                }
                __syncthreads();
                int c = tid & 31, w = tid >> 5, d = d0 + c;
                u64 acc[NP];
#pragma unroll
                for (int p = 0; p < NP; p++) acc[p] = 0;
#pragma unroll 2
                for (int nn = 0; nn < 24; nn++) {
                    int n = w * 24 + nn;
                    u64 bw = pk2(g_v[ko + (size_t)n * D_ + d]);
#pragma unroll
                    for (int p = 0; p < NP; p++) fma2p(acc[p], at2[p * N_ + n], bw);
                }
#pragma unroll
                for (int p = 0; p < NP; p++) part[(w * NP + p) * 32 + c] = acc[p];
                __syncthreads();
                for (int o = tid; o < NP * 32; o += 256) {
                    int p = o >> 5, cc = o & 31;
                    float2 s = make_float2(0.f, 0.f);
#pragma unroll
                    for (int w2 = 0; w2 < 8; w2++) {
                        float2 v = upk(part[(w2 * NP + p) * 32 + cc]);
                        s.x += v.x; s.y += v.y;
                    }
                    g_upd[so + (size_t)(2 * p) * D_ + d0 + cc] = s.x * rinv[2 * p];
                    if (2 * p + 1 < S_)
                        g_upd[so + (size_t)(2 * p + 1) * D_ + d0 + cc] = s.y * rinv[2 * p + 1];
                }
            }
            bsync(bb);

            /* =============== gi/gh + GRU: cols [d0,d0+32) ============ */
            {
                u64* a2u = (u64*)sh;              /* 11*256 */
                u64* a2s = (u64*)(sh + 5632);     /* 11*256 */
                u64* part = (u64*)(sh + 11264);   /* 8*11*32 */
                u64* gates = (u64*)(sh + 16896);  /* 6*11*32 */
                pack21g(g_upd + so, a2u, tid);
                pack21g(g_slots + so, a2s, tid);
                __syncthreads();
                int c = tid & 31, w = tid >> 5;
#pragma unroll 1
                for (int sub = 0; sub < 6; sub++) {
                    const u64* a2 = (sub < 3) ? a2u : a2s;
                    const float* wt = (sub < 3) ? g_wiht : g_whht;
                    int gcol = (sub % 3) * 256 + d0 + c;
                    u64 acc[NP];
#pragma unroll
                    for (int p = 0; p < NP; p++) acc[p] = 0;
#pragma unroll 4
                    for (int kk = 0; kk < 32; kk++) {
                        int k = w * 32 + kk;
                        u64 bw = pk2(wt[k * 768 + gcol]);
#pragma unroll
                        for (int p = 0; p < NP; p++) fma2p(acc[p], a2[p * 256 + k], bw);
                    }
#pragma unroll
                    for (int p = 0; p < NP; p++) part[(w * NP + p) * 32 + c] = acc[p];
                    __syncthreads();
                    const float* bias = (sub < 3) ? bih : bhh;
                    for (int o = tid; o < NP * 32; o += 256) {
                        int p = o >> 5, cc = o & 31;
                        float2 s = make_float2(0.f, 0.f);
#pragma unroll
                        for (int w2 = 0; w2 < 8; w2++) {
                            float2 v = upk(part[(w2 * NP + p) * 32 + cc]);
                            s.x += v.x; s.y += v.y;
                        }
                        float bv2 = bias[(sub % 3) * 256 + d0 + cc];
                        s.x += bv2; s.y += bv2;
                        gates[(sub * NP + p) * 32 + cc] = *(u64*)&s;
                    }
                    __syncthreads();
                }
                /* GRU pointwise on local cols */
                for (int o = tid; o < NP * 32; o += 256) {
                    int p = o >> 5, cc = o & 31;
                    float2 ir = upk(gates[(0 * NP + p) * 32 + cc]);
                    float2 iz = upk(gates[(1 * NP + p) * 32 + cc]);
                    float2 in_ = upk(gates[(2 * NP + p) * 32 + cc]);
                    float2 hr = upk(gates[(3 * NP + p) * 32 + cc]);
                    float2 hz = upk(gates[(4 * NP + p) * 32 + cc]);
                    float2 hn = upk(gates[(5 * NP + p) * 32 + cc]);
                    float2 sl = upk(a2s[p * 256 + d0 + cc]);
                    float r0 = sigm(ir.x + hr.x), z0 = sigm(iz.x + hz.x);
                    float n0 = tanhf(in_.x + r0 * hn.x);
                    g_h[so + (size_t)(2 * p) * D_ + d0 + cc] = (1.f - z0) * n0 + z0 * sl.x;
                    if (2 * p + 1 < S_) {
                        float r1 = sigm(ir.y + hr.y), z1 = sigm(iz.y + hz.y);
                        float n1 = tanhf(in_.y + r1 * hn.y);
                        g_h[so + (size_t)(2 * p + 1) * D_ + d0 + cc] = (1.f - z1) * n1 + z1 * sl.y;
                    }
                }
            }
            bsync(bb);

            /* =============== ffLN + W1 (relu): cols [d0,d0+32) ======= */
            {
                float* raw = sh;
                u64* a2h = (u64*)(sh + 5376);
                u64* part = (u64*)(sh + 11008);
#pragma unroll 1
                for (int r = wid; r < S_; r += 8) {
                    float o[8];
                    ln_row(g_h + so + (size_t)r * D_, gff, beff, lane, o);
                    *(float4*)(raw + r * 256 + lane * 8) = make_float4(o[0], o[1], o[2], o[3]);
                    *(float4*)(raw + r * 256 + lane * 8 + 4) = make_float4(o[4], o[5], o[6], o[7]);
                }
                __syncthreads();
                pack21(raw, a2h, tid);
                __syncthreads();
                int c = tid & 31, w = tid >> 5, col = d0 + c;
                u64 acc[NP];
#pragma unroll
                for (int p = 0; p < NP; p++) acc[p] = 0;
#pragma unroll 4
                for (int kk = 0; kk < 32; kk++) {
                    int k = w * 32 + kk;
                    u64 bw = pk2(g_w1t[k * 256 + col]);
#pragma unroll
                    for (int p = 0; p < NP; p++) fma2p(acc[p], a2h[p * 256 + k], bw);
                }
#pragma unroll
                for (int p = 0; p < NP; p++) part[(w * NP + p) * 32 + c] = acc[p];
                __syncthreads();
                for (int o = tid; o < NP * 32; o += 256) {
                    int p = o >> 5, cc = o & 31;
                    float2 s = make_float2(0.f, 0.f);
#pragma unroll
                    for (int w2 = 0; w2 < 8; w2++) {
                        float2 v = upk(part[(w2 * NP + p) * 32 + cc]);
                        s.x += v.x; s.y += v.y;
                    }
                    float bias = b1[d0 + cc];
                    g_hidden[so + (size_t)(2 * p) * D_ + d0 + cc] = fmaxf(s.x + bias, 0.f);
                    if (2 * p + 1 < S_)
                        g_hidden[so + (size_t)(2 * p + 1) * D_ + d0 + cc] = fmaxf(s.y + bias, 0.f);
                }
            }
            bsync(bb);

            /* =============== W2 + residual -> slots ================== */
            {
                u64* a2 = (u64*)sh;
                u64* part = (u64*)(sh + 5632);
                pack21g(g_hidden + so, a2, tid);
                __syncthreads();
                int c = tid & 31, w = tid >> 5, col = d0 + c;
                u64 acc[NP];
#pragma unroll
                for (int p = 0; p < NP; p++) acc[p] = 0;
#pragma unroll 4
                for (int kk = 0; kk < 32; kk++) {
                    int k = w * 32 + kk;
                    u64 bw = pk2(g_w2t[k * 256 + col]);
#pragma unroll
                    for (int p = 0; p < NP; p++) fma2p(acc[p], a2[p * 256 + k], bw);
                }
#pragma unroll
                for (int p = 0; p < NP; p++) part[(w * NP + p) * 32 + c] = acc[p];
                __syncthreads();
                for (int o = tid; o < NP * 32; o += 256) {
                    int p = o >> 5, cc = o & 31;
                    float2 s = make_float2(0.f, 0.f);
#pragma unroll
                    for (int w2 = 0; w2 < 8; w2++) {
                        float2 v = upk(part[(w2 * NP + p) * 32 + cc]);
                        s.x += v.x; s.y += v.y;
                    }
                    float bias = b2[d0 + cc];
                    g_slots[so + (size_t)(2 * p) * D_ + d0 + cc] =
                        s.x + bias + g_h[so + (size_t)(2 * p) * D_ + d0 + cc];
                    if (2 * p + 1 < S_)
                        g_slots[so + (size_t)(2 * p + 1) * D_ + d0 + cc] =
                            s.y + bias + g_h[so + (size_t)(2 * p + 1) * D_ + d0 + cc];
                }
            }
            bsync(bb);
        }
    }

    /* final: first 20 slots of this batch */
    for (int r = j; r < 20; r += 8)
        out_slots[((size_t)bb * 20 + r) * D_ + tid] = g_slots[so + (size_t)r * D_ + tid];
}

/* ------------------------------------------------------------------ */
extern "C" void kernel_launch(void* const* d_in, const int* in_sizes, int n_in,
                              void* d_out, int out_size) {
    const float* inputs = (const float*)d_in[0];
    const float* noise  = (const float*)d_in[1];
    const float* mu     = (const float*)d_in[2];
    const float* sigma  = (const float*)d_in[3];
    const float* Wq = (const float*)d_in[4];  const float* bq = (const float*)d_in[5];
    const float* Wk = (const float*)d_in[6];  const float* bk = (const float*)d_in[7];
    const float* Wv = (const float*)d_in[8];  const float* bv = (const float*)d_in[9];
    const float* W1 = (const float*)d_in[10]; const float* b1 = (const float*)d_in[11];
    const float* W2 = (const float*)d_in[12]; const float* b2 = (const float*)d_in[13];
    const float* Wih = (const float*)d_in[14]; const float* bih = (const float*)d_in[15];
    const float* Whh = (const float*)d_in[16]; const float* bhh = (const float*)d_in[17];
    const float* gin = (const float*)d_in[18]; const float* bein = (const float*)d_in[19];
    const float* gsl = (const float*)d_in[20]; const float* besl = (const float*)d_in[21];
    const float* gff = (const float*)d_in[22]; const float* beff = (const float*)d_in[23];

    float* out = (float*)d_out;
    float* out_slots = out;
    float* out_attn = out + (size_t)B_ * 20 * D_;

    cudaFuncSetAttribute(mega_kernel, cudaFuncAttributeMaxDynamicSharedMemorySize,
                         SMEM_BYTES);

    mega_kernel<<<NBLK, 256, SMEM_BYTES>>>(inputs, noise, mu, sigma,
                                           Wq, bq, Wk, bk, Wv, bv, W1, b1, W2, b2,
                                           Wih, bih, Whh, bhh,
                                           gin, bein, gsl, besl, gff, beff,
                                           out_slots, out_attn);
}